// round 5
// baseline (speedup 1.0000x reference)
#include <cuda_runtime.h>
#include <math.h>

#define BB 64
#define FF 512
#define EE 256
#define HH 8
#define DD 32
#define LL 4

// Precomputed collapsed vectors + handshake (device globals; zero-initialized)
__device__ float g_kw[EE];   // emb_w @ k_w
__device__ float g_vw[EE];   // emb_w @ v_w
__device__ float g_vb[EE];   // emb_b @ v_w + v_b
__device__ float g_qv[EE];   // emb_b @ q_w + q_b
__device__ unsigned int g_flag = 0;   // producers released (target 32)
__device__ unsigned int g_done = 0;   // consumers retired  (target 64)

__device__ __forceinline__ float ex2f(float x) {
    float y;
    asm("ex2.approx.ftz.f32 %0, %1;" : "=f"(y) : "f"(x));
    return y;
}
__device__ __forceinline__ void flag_release_add1() {
    asm volatile("red.release.gpu.global.add.u32 [%0], %1;"
                 :: "l"(&g_flag), "r"(1u) : "memory");
}
__device__ __forceinline__ unsigned int flag_acquire_load() {
    unsigned int v;
    asm volatile("ld.acquire.gpu.global.u32 %0, [%1];"
                 : "=r"(v) : "l"(&g_flag) : "memory");
    return v;
}

// ---------------------------------------------------------------------------
// Single fused kernel, grid = 96 (one wave), block = 256.
//   blocks 64..95 : producers — one precompute unit each (matrix m, col grp),
//                   release via red.release, then exit.
//   blocks  0..63 : consumers — one batch each; full prologue BEFORE the gate
//                   so the producer latency is overlapped, then the L=4
//                   warp-local recursion per head.
// ---------------------------------------------------------------------------
__global__ void __launch_bounds__(256, 1)
fused_kernel(const float* __restrict__ features,
             const float* __restrict__ emb_w,
             const float* __restrict__ emb_b,
             const float* __restrict__ q_w,
             const float* __restrict__ q_b,
             const float* __restrict__ k_w,
             const float* __restrict__ v_w,
             const float* __restrict__ v_b,
             const float* __restrict__ attn_w,
             const float* __restrict__ attn_b,
             float* __restrict__ out) {
    const int b    = blockIdx.x;
    const int t    = threadIdx.x;       // 0..255
    const int warp = t >> 5;
    const int lane = t & 31;

    if (b >= BB) {
        // ------------------- producer block -------------------
        __shared__ float s_pre[8][32];
        const int p   = b - BB;           // 0..31
        const int m   = p >> 3;           // 0:kw 1:vw 2:vb 3:qv
        const int grp = p & 7;
        const int col = grp * 32 + lane;
        const float* vecsrc = (m <= 1) ? emb_w : emb_b;
        const float* mat    = (m == 0) ? k_w : (m == 3 ? q_w : v_w);

        float ev = vecsrc[warp * 32 + lane];
        const float* mp = mat + (warp * 32) * EE + col;
        float acc = 0.f;
        #pragma unroll
        for (int e = 0; e < 32; e++)
            acc = fmaf(__shfl_sync(0xffffffffu, ev, e), mp[e * EE], acc);
        s_pre[warp][lane] = acc;
        __syncthreads();

        if (t < 32) {
            float a = 0.f;
            #pragma unroll
            for (int r = 0; r < 8; r++) a += s_pre[r][lane];
            if (m == 2) a += v_b[col];
            if (m == 3) a += q_b[col];
            float* dst = (m == 0) ? g_kw : (m == 1) ? g_vw
                       : (m == 2) ? g_vb : g_qv;
            dst[col] = a;
            __threadfence();              // writer-side fence (gpu scope)
        }
        __syncthreads();                  // fences done before release
        if (t == 0) flag_release_add1();
        return;
    }

    // ------------------- consumer block -------------------
    __shared__ float s_ox[HH], s_hc[HH];

    // Full feature vector per warp: xr[i] = x[lane + 32i] (coalesced)
    const float* xb = features + b * FF;
    float xr[FF / 32];
    #pragma unroll
    for (int i = 0; i < FF / 32; i++) xr[i] = xb[lane + i * 32];

    const int hi = warp * DD + lane;
    float aw = attn_w[hi];
    float ab = attn_b[0];

    // Warp-local stats (independent of g_*, overlaps producer latency)
    float S = 0.f, xmax = -1e30f, xmin = 1e30f;
    #pragma unroll
    for (int i = 0; i < FF / 32; i++) {
        S += xr[i];
        xmax = fmaxf(xmax, xr[i]);
        xmin = fminf(xmin, xr[i]);
    }
    #pragma unroll
    for (int o = 16; o > 0; o >>= 1) {
        S   += __shfl_xor_sync(0xffffffffu, S,   o);
        xmax = fmaxf(xmax, __shfl_xor_sync(0xffffffffu, xmax, o));
        xmin = fminf(xmin, __shfl_xor_sync(0xffffffffu, xmin, o));
    }

    // ---- Gate: wait until all 32 producers released ----
    if (t == 0) {
        while (flag_acquire_load() < 32u) { }
    }
    __syncthreads();

    // ---- Per-head scalars ----
    float kw = __ldcg(&g_kw[hi]);
    float vw = __ldcg(&g_vw[hi]);
    float vb = __ldcg(&g_vb[hi]);
    float qv = __ldcg(&g_qv[hi]);

    const float scale = 0.17677669529663687f;      // 1/sqrt(32)
    float A0 = qv * kw, P = vw * kw, R = vb * kw, VA = vw * aw, VB = vb * aw;
    #pragma unroll
    for (int o = 16; o > 0; o >>= 1) {
        A0 += __shfl_xor_sync(0xffffffffu, A0, o);
        P  += __shfl_xor_sync(0xffffffffu, P,  o);
        R  += __shfl_xor_sync(0xffffffffu, R,  o);
        VA += __shfl_xor_sync(0xffffffffu, VA, o);
        VB += __shfl_xor_sync(0xffffffffu, VB, o);
    }
    A0 *= scale; P *= scale; R *= scale;

    // ---- L-step scalar softmax recursion (warp-local) ----
    const float L2E = 1.4426950408889634f;
    float alpha = A0;
    float m = 0.f;
    #pragma unroll
    for (int it = 0; it < LL; it++) {
        float a2 = alpha * L2E;
        float M2 = (alpha >= 0.f) ? a2 * xmax : a2 * xmin;   // exact max logit
        float sw = 0.f, sxw = 0.f;
        #pragma unroll
        for (int i = 0; i < FF / 32; i++) {
            float w = ex2f(fmaf(a2, xr[i], -M2));
            sw += w;
            sxw = fmaf(xr[i], w, sxw);
        }
        #pragma unroll
        for (int o = 16; o > 0; o >>= 1) {
            sw  += __shfl_xor_sync(0xffffffffu, sw,  o);
            sxw += __shfl_xor_sync(0xffffffffu, sxw, o);
        }
        m = __fdividef(sxw, sw);
        alpha = fmaf(m, P, R);
    }

    if (lane == 0) {
        s_ox[warp] = fmaf(m, VA, VB);                          // Qc contribution
        s_hc[warp] = fmaf(S - m, VA, (float)(FF - 1) * VB);    // (v_sum - Qc)
    }
    __syncthreads();

    float ox = ab, cc = ab;
    #pragma unroll
    for (int hh = 0; hh < HH; hh++) { ox += s_ox[hh]; cc += s_hc[hh]; }

    out[b * FF + t]                 = ox;
    out[b * FF + t + 256]           = ox;
    out[BB * FF + b * FF + t]       = cc;
    out[BB * FF + b * FF + t + 256] = cc;

    // ---- Last consumer resets flags for the next graph replay.
    // Safe: g_done reaches 64 only after every consumer passed the gate.
    if (t == 0) {
        unsigned int prev = atomicAdd(&g_done, 1u);
        if (prev == BB - 1) {
            g_flag = 0u;
            g_done = 0u;
            __threadfence();
        }
    }
}

extern "C" void kernel_launch(void* const* d_in, const int* in_sizes, int n_in,
                              void* d_out, int out_size) {
    const float* features = (const float*)d_in[0];
    const float* emb_w    = (const float*)d_in[1];
    const float* emb_b    = (const float*)d_in[2];
    const float* q_w      = (const float*)d_in[3];
    const float* q_b      = (const float*)d_in[4];
    const float* k_w      = (const float*)d_in[5];
    // d_in[6] = k_b: cancels in softmax, unused
    const float* v_w      = (const float*)d_in[7];
    const float* v_b      = (const float*)d_in[8];
    const float* attn_w   = (const float*)d_in[9];
    const float* attn_b   = (const float*)d_in[10];
    float* out = (float*)d_out;

    fused_kernel<<<96, 256>>>(features, emb_w, emb_b, q_w, q_b, k_w,
                              v_w, v_b, attn_w, attn_b, out);
}